// round 3
// baseline (speedup 1.0000x reference)
#include <cuda_runtime.h>

#define BATCH 8
#define CD 256
#define CS 512
#define MPTS 4096
#define SPTS 1024
#define NPTS 4096
#define KNN 3
#define WLD 768   // conv_w row length (3*Cd)

#define BM 64
#define BN 64
#define BK 16

// ---------------- scratch (device globals; no allocation allowed) -------------
__device__ float g_z[BATCH * CD * SPTS];         // (W2 @ sparse_data): [b][o][s]   8 MB
__device__ float g_y[(size_t)BATCH * CD * MPTS]; // pre-BN output  [b][o][m]       32 MB
__device__ int   g_ki[BATCH * MPTS * KNN];
__device__ float g_kw[BATCH * MPTS * KNN];
__device__ float g_scale[CD];
__device__ float g_bias[CD];

// ---------------- kernel 1: KNN (k=3) over gathered xyz ----------------------
// Bit-matches the reference XLA fusion:
//   A = x^2+y^2+z^2 (plain rn products, sequential rn adds)
//   E = rn(rn(rn(x*x') + rn(y*y')) + rn(z*z'))   -- NO fma contraction
//   d2 = rn(rn(A + B) - rn(2*E))
// Ties broken toward lower index (strict < insertion), matching lax.top_k.
__global__ __launch_bounds__(256) void knn_kernel(
    const float* __restrict__ pcd,
    const int* __restrict__ dense_idx,
    const int* __restrict__ sparse_idx)
{
    __shared__ float sx[SPTS], sy[SPTS], sz[SPTS], ss[SPTS];
    const int b = blockIdx.y;
    const float* pb = pcd + (size_t)b * 3 * NPTS;

    for (int s = threadIdx.x; s < SPTS; s += blockDim.x) {
        int si = sparse_idx[b * SPTS + s];
        float x = pb[si], y = pb[NPTS + si], z = pb[2 * NPTS + si];
        ss[s] = __fadd_rn(__fadd_rn(__fmul_rn(x, x), __fmul_rn(y, y)), __fmul_rn(z, z));
        sx[s] = x; sy[s] = y; sz[s] = z;
    }
    __syncthreads();

    const int m = blockIdx.x * blockDim.x + threadIdx.x;
    const int di = dense_idx[b * MPTS + m];
    const float dx = pb[di], dy = pb[NPTS + di], dz = pb[2 * NPTS + di];
    const float dd = __fadd_rn(__fadd_rn(__fmul_rn(dx, dx), __fmul_rn(dy, dy)),
                               __fmul_rn(dz, dz));

    float d0 = 3.4e38f, d1 = 3.4e38f, d2v = 3.4e38f;
    int i0 = 0, i1 = 0, i2 = 0;
    #pragma unroll 4
    for (int s = 0; s < SPTS; s++) {
        float p0 = __fmul_rn(dx, sx[s]);
        float p1 = __fmul_rn(dy, sy[s]);
        float p2 = __fmul_rn(dz, sz[s]);
        float dot = __fadd_rn(__fadd_rn(p0, p1), p2);
        float d2 = __fadd_rn(__fadd_rn(dd, ss[s]), -__fmul_rn(2.0f, dot));
        if (d2 < d0)       { d2v = d1; i2 = i1; d1 = d0; i1 = i0; d0 = d2; i0 = s; }
        else if (d2 < d1)  { d2v = d1; i2 = i1; d1 = d2; i1 = s; }
        else if (d2 < d2v) { d2v = d2; i2 = s; }
    }
    // weights exactly as reference: w = 1/(d+EPS); w = w / sum(w)
    float w0 = __fdiv_rn(1.0f, __fadd_rn(d0,  1e-8f));
    float w1 = __fdiv_rn(1.0f, __fadd_rn(d1,  1e-8f));
    float w2 = __fdiv_rn(1.0f, __fadd_rn(d2v, 1e-8f));
    float sum = __fadd_rn(__fadd_rn(w0, w1), w2);
    int base = (b * MPTS + m) * KNN;
    g_ki[base + 0] = i0; g_ki[base + 1] = i1; g_ki[base + 2] = i2;
    g_kw[base + 0] = __fdiv_rn(w0, sum);
    g_kw[base + 1] = __fdiv_rn(w1, sum);
    g_kw[base + 2] = __fdiv_rn(w2, sum);
}

// ---------------- shared-memory tiled fp32 GEMM ------------------------------
// C[b][o][m] = sum_c conv_w[o][WOFF + c] * Xg[b][c][m]   (+ optional knn epilogue)
template<int KDIM, int WOFF, int LDX, bool EPI>
__global__ __launch_bounds__(256) void gemm_kernel(
    const float* __restrict__ conv_w,
    const float* __restrict__ Xg)
{
    __shared__ float Ws[BM][BK + 1];   // [o][k]
    __shared__ float Xs[BK][BN];       // [k][m]

    const int b  = blockIdx.z;
    const int m0 = blockIdx.x * BN;
    const int o0 = blockIdx.y * BM;
    const float* X = Xg + (size_t)b * KDIM * LDX;

    const int tid = threadIdx.x;
    const int tx = tid & 15;        // m group
    const int ty = tid >> 4;        // o group
    const int wo = tid >> 2;        // W load: row within tile
    const int wk = tid & 3;         // W load: k quad
    const int xk = tid >> 4;        // X load: k row
    const int xm = tid & 15;        // X load: m quad

    float acc[4][4];
    #pragma unroll
    for (int i = 0; i < 4; i++)
        #pragma unroll
        for (int j = 0; j < 4; j++) acc[i][j] = 0.0f;

    for (int kt = 0; kt < KDIM; kt += BK) {
        float4 w4 = *(const float4*)&conv_w[(size_t)(o0 + wo) * WLD + WOFF + kt + wk * 4];
        float4 x4 = *(const float4*)&X[(size_t)(kt + xk) * LDX + m0 + xm * 4];
        __syncthreads();
        Ws[wo][wk * 4 + 0] = w4.x;
        Ws[wo][wk * 4 + 1] = w4.y;
        Ws[wo][wk * 4 + 2] = w4.z;
        Ws[wo][wk * 4 + 3] = w4.w;
        *(float4*)&Xs[xk][xm * 4] = x4;
        __syncthreads();

        #pragma unroll
        for (int k = 0; k < BK; k++) {
            float4 xv = *(const float4*)&Xs[k][tx * 4];
            float w0v = Ws[ty * 4 + 0][k];
            float w1v = Ws[ty * 4 + 1][k];
            float w2v = Ws[ty * 4 + 2][k];
            float w3v = Ws[ty * 4 + 3][k];
            acc[0][0] += w0v * xv.x; acc[0][1] += w0v * xv.y; acc[0][2] += w0v * xv.z; acc[0][3] += w0v * xv.w;
            acc[1][0] += w1v * xv.x; acc[1][1] += w1v * xv.y; acc[1][2] += w1v * xv.z; acc[1][3] += w1v * xv.w;
            acc[2][0] += w2v * xv.x; acc[2][1] += w2v * xv.y; acc[2][2] += w2v * xv.z; acc[2][3] += w2v * xv.w;
            acc[3][0] += w3v * xv.x; acc[3][1] += w3v * xv.y; acc[3][2] += w3v * xv.z; acc[3][3] += w3v * xv.w;
        }
    }

    if (EPI) {
        // add knn-interpolated contribution: sum_k w_k * z[b][o][idx_k]
        int   ii[4][3];
        float ww[4][3];
        #pragma unroll
        for (int j = 0; j < 4; j++) {
            int mcol = m0 + tx * 4 + j;
            int base = (b * MPTS + mcol) * KNN;
            #pragma unroll
            for (int k = 0; k < KNN; k++) {
                ii[j][k] = g_ki[base + k];
                ww[j][k] = g_kw[base + k];
            }
        }
        #pragma unroll
        for (int i = 0; i < 4; i++) {
            const float* zrow = g_z + (size_t)(b * CD + o0 + ty * 4 + i) * SPTS;
            #pragma unroll
            for (int j = 0; j < 4; j++) {
                acc[i][j] += ww[j][0] * zrow[ii[j][0]]
                           + ww[j][1] * zrow[ii[j][1]]
                           + ww[j][2] * zrow[ii[j][2]];
            }
        }
    }

    float* C = EPI ? g_y : g_z;
    const int ldc = EPI ? MPTS : SPTS;
    #pragma unroll
    for (int i = 0; i < 4; i++) {
        float4 v = make_float4(acc[i][0], acc[i][1], acc[i][2], acc[i][3]);
        *(float4*)&C[(size_t)(b * CD + o0 + ty * 4 + i) * ldc + m0 + tx * 4] = v;
    }
}

// ---------------- kernel 4: BN statistics per output channel -----------------
__global__ __launch_bounds__(256) void bn_stats_kernel(
    const float* __restrict__ gamma,
    const float* __restrict__ beta)
{
    const int o = blockIdx.x;
    float s = 0.0f, s2 = 0.0f;
    for (int flat = threadIdx.x; flat < BATCH * MPTS; flat += blockDim.x) {
        int b = flat >> 12;
        int m = flat & (MPTS - 1);
        float v = g_y[(size_t)(b * CD + o) * MPTS + m];
        s += v; s2 += v * v;
    }
    __shared__ float sh[256], sh2[256];
    sh[threadIdx.x] = s; sh2[threadIdx.x] = s2;
    __syncthreads();
    for (int off = 128; off > 0; off >>= 1) {
        if (threadIdx.x < off) {
            sh[threadIdx.x]  += sh[threadIdx.x + off];
            sh2[threadIdx.x] += sh2[threadIdx.x + off];
        }
        __syncthreads();
    }
    if (threadIdx.x == 0) {
        const float invn = 1.0f / (float)(BATCH * MPTS);
        float mean = sh[0] * invn;
        float var  = sh2[0] * invn - mean * mean;
        float sc = gamma[o] * rsqrtf(var + 1e-5f);
        g_scale[o] = sc;
        g_bias[o]  = beta[o] - mean * sc;
    }
}

// ---------------- kernel 5: normalize + LeakyReLU ----------------------------
__global__ __launch_bounds__(256) void bn_apply_kernel(float* __restrict__ out)
{
    const size_t total4 = (size_t)BATCH * CD * MPTS / 4;
    size_t i4 = (size_t)blockIdx.x * blockDim.x + threadIdx.x;
    if (i4 >= total4) return;
    float4 v = ((const float4*)g_y)[i4];
    int o = (int)((i4 >> 10) & (CD - 1));
    float sc = g_scale[o], bi = g_bias[o];
    float t;
    t = v.x * sc + bi; v.x = (t >= 0.0f) ? t : 0.2f * t;
    t = v.y * sc + bi; v.y = (t >= 0.0f) ? t : 0.2f * t;
    t = v.z * sc + bi; v.z = (t >= 0.0f) ? t : 0.2f * t;
    t = v.w * sc + bi; v.w = (t >= 0.0f) ? t : 0.2f * t;
    ((float4*)out)[i4] = v;
}

// second tuple element: dense_idx appended after y, as float
__global__ __launch_bounds__(256) void idx_copy_kernel(
    const int* __restrict__ dense_idx, float* __restrict__ out)
{
    int j = blockIdx.x * blockDim.x + threadIdx.x;
    if (j < BATCH * MPTS)
        out[(size_t)BATCH * CD * MPTS + j] = (float)dense_idx[j];
}

// ---------------- host launcher ----------------------------------------------
extern "C" void kernel_launch(void* const* d_in, const int* in_sizes, int n_in,
                              void* d_out, int out_size)
{
    const float* dense_data  = (const float*)d_in[0];
    const int*   dense_idx   = (const int*)  d_in[1];
    const float* sparse_data = (const float*)d_in[2];
    const int*   sparse_idx  = (const int*)  d_in[3];
    const float* pcd         = (const float*)d_in[4];
    const float* conv_w      = (const float*)d_in[5];
    const float* bn_gamma    = (const float*)d_in[6];
    const float* bn_beta     = (const float*)d_in[7];
    float* out = (float*)d_out;

    // 1. KNN indices + weights
    knn_kernel<<<dim3(MPTS / 256, BATCH), 256>>>(pcd, dense_idx, sparse_idx);

    // 2. z = W[:,256:768] @ sparse_data   (K=512, cols=1024)
    gemm_kernel<CS, CD, SPTS, false>
        <<<dim3(SPTS / BN, CD / BM, BATCH), 256>>>(conv_w, sparse_data);

    // 3. y = W[:,0:256] @ dense_data + knn-gather(z)   (K=256, cols=4096)
    gemm_kernel<CD, 0, MPTS, true>
        <<<dim3(MPTS / BN, CD / BM, BATCH), 256>>>(conv_w, dense_data);

    // 4. batch-norm statistics
    bn_stats_kernel<<<CD, 256>>>(bn_gamma, bn_beta);

    // 5. normalize + leaky relu
    size_t total4 = (size_t)BATCH * CD * MPTS / 4;
    bn_apply_kernel<<<(unsigned)((total4 + 255) / 256), 256>>>(out);

    // 6. tuple tail: dense_idx
    if (out_size >= BATCH * CD * MPTS + BATCH * MPTS)
        idx_copy_kernel<<<(BATCH * MPTS + 255) / 256, 256>>>(dense_idx, out);
}

// round 5
// speedup vs baseline: 1.7787x; 1.7787x over previous
#include <cuda_runtime.h>

#define BATCH 8
#define CD 256
#define CS 512
#define MPTS 4096
#define SPTS 1024
#define NPTS 4096
#define WLD 768

typedef unsigned int u32;

// ---------------- scratch (device globals) -----------------------------------
__device__ float g_z[BATCH * CD * SPTS];          // W2 @ sparse : [b][o][s]
__device__ float g_y[(size_t)BATCH * CD * MPTS];  // pre-BN y    : [b][o][m]
__device__ int   g_ki[BATCH * MPTS * 3];
__device__ float g_kw[BATCH * MPTS * 3];
__device__ float g_rsum[BATCH * CD];
__device__ float g_rsum2[BATCH * CD];
__device__ float g_scale[CD];
__device__ float g_bias[CD];

__device__ __forceinline__ float tf32rn(float x) {
    float y;
    asm("cvt.rna.tf32.f32 %0, %1;" : "=f"(y) : "f"(x));
    return y;
}

// ---------------- kernel 1: KNN (exact fp32, bit-matches reference) -----------
__global__ __launch_bounds__(256) void knn_kernel(
    const float* __restrict__ pcd,
    const int* __restrict__ dense_idx,
    const int* __restrict__ sparse_idx)
{
    __shared__ float sx[SPTS], sy[SPTS], sz[SPTS], ss[SPTS];
    const int b = blockIdx.y;
    const float* pb = pcd + (size_t)b * 3 * NPTS;

    for (int s = threadIdx.x; s < SPTS; s += blockDim.x) {
        int si = sparse_idx[b * SPTS + s];
        float x = pb[si], y = pb[NPTS + si], z = pb[2 * NPTS + si];
        ss[s] = __fadd_rn(__fadd_rn(__fmul_rn(x, x), __fmul_rn(y, y)), __fmul_rn(z, z));
        sx[s] = x; sy[s] = y; sz[s] = z;
    }
    __syncthreads();

    const int m = blockIdx.x * blockDim.x + threadIdx.x;
    const int di = dense_idx[b * MPTS + m];
    const float dx = pb[di], dy = pb[NPTS + di], dz = pb[2 * NPTS + di];
    const float dd = __fadd_rn(__fadd_rn(__fmul_rn(dx, dx), __fmul_rn(dy, dy)),
                               __fmul_rn(dz, dz));

    float d0 = 3.4e38f, d1 = 3.4e38f, d2v = 3.4e38f;
    int i0 = 0, i1 = 0, i2 = 0;
    #pragma unroll 4
    for (int s = 0; s < SPTS; s++) {
        float p0 = __fmul_rn(dx, sx[s]);
        float p1 = __fmul_rn(dy, sy[s]);
        float p2 = __fmul_rn(dz, sz[s]);
        float dot = __fadd_rn(__fadd_rn(p0, p1), p2);
        float d2 = __fadd_rn(__fadd_rn(dd, ss[s]), -__fmul_rn(2.0f, dot));
        if (d2 < d0)       { d2v = d1; i2 = i1; d1 = d0; i1 = i0; d0 = d2; i0 = s; }
        else if (d2 < d1)  { d2v = d1; i2 = i1; d1 = d2; i1 = s; }
        else if (d2 < d2v) { d2v = d2; i2 = s; }
    }
    float w0 = __fdiv_rn(1.0f, __fadd_rn(d0,  1e-8f));
    float w1 = __fdiv_rn(1.0f, __fadd_rn(d1,  1e-8f));
    float w2 = __fdiv_rn(1.0f, __fadd_rn(d2v, 1e-8f));
    float sum = __fadd_rn(__fadd_rn(w0, w1), w2);
    int base = (b * MPTS + m) * 3;
    g_ki[base + 0] = i0; g_ki[base + 1] = i1; g_ki[base + 2] = i2;
    g_kw[base + 0] = __fdiv_rn(w0, sum);
    g_kw[base + 1] = __fdiv_rn(w1, sum);
    g_kw[base + 2] = __fdiv_rn(w2, sum);
}

// ---------------- tf32 mma.sync GEMM ------------------------------------------
// out[b][o0+r][m0+c] = sum_k conv_w[o0+r][WOFF+k] * Xg[b][k][m0+c]
// Block tile 128(o) x 128(m), 8 warps of 64x32, BK=32, mma m16n8k8 tf32.
#define BKK 32
#define APAD 36    // A smem row pitch  (o-major [128][36])
#define BPAD 136   // B smem row pitch  (k-major [32][136])

template<int KDIM, int WOFF, int LDXV>
__global__ __launch_bounds__(256) void gemm_mma(
    const float* __restrict__ conv_w,
    const float* __restrict__ Xg,
    float* __restrict__ outp, int ldc)
{
    __shared__ float Asm[128 * APAD];
    __shared__ float Bsm[BKK * BPAD];

    const int tid  = threadIdx.x;
    const int wid  = tid >> 5;
    const int lane = tid & 31;
    const int lq   = lane >> 2;   // 0..7
    const int ls   = lane & 3;    // 0..3
    const int wo   = (wid >> 2) * 64;   // warp o-offset within tile
    const int wm   = (wid & 3) * 32;    // warp m-offset within tile

    const int b  = blockIdx.z;
    const int o0 = blockIdx.y * 128;
    const int m0 = blockIdx.x * 128;
    const float* X = Xg + (size_t)b * KDIM * LDXV;

    float c[4][4][4];
    #pragma unroll
    for (int mt = 0; mt < 4; mt++)
        #pragma unroll
        for (int nt = 0; nt < 4; nt++)
            #pragma unroll
            for (int r = 0; r < 4; r++) c[mt][nt][r] = 0.0f;

    for (int kt = 0; kt < KDIM; kt += BKK) {
        if (kt) __syncthreads();
        // load A chunk: W[o0..o0+127][WOFF+kt .. +31] -> Asm[o][k], tf32-rounded
        #pragma unroll
        for (int q = 0; q < 4; q++) {
            int f = tid + q * 256;          // 0..1023 float4 units
            int o = f >> 3, k4 = f & 7;
            float4 v = *(const float4*)&conv_w[(size_t)(o0 + o) * WLD + WOFF + kt + k4 * 4];
            float* dst = &Asm[o * APAD + k4 * 4];
            dst[0] = tf32rn(v.x); dst[1] = tf32rn(v.y);
            dst[2] = tf32rn(v.z); dst[3] = tf32rn(v.w);
        }
        // load B chunk: X[kt..kt+31][m0..m0+127] -> Bsm[k][m], tf32-rounded
        #pragma unroll
        for (int q = 0; q < 4; q++) {
            int f = tid + q * 256;          // 0..1023 float4 units
            int k = f >> 5, m4 = f & 31;
            float4 v = *(const float4*)&X[(size_t)(kt + k) * LDXV + m0 + m4 * 4];
            float* dst = &Bsm[k * BPAD + m4 * 4];
            dst[0] = tf32rn(v.x); dst[1] = tf32rn(v.y);
            dst[2] = tf32rn(v.z); dst[3] = tf32rn(v.w);
        }
        __syncthreads();

        #pragma unroll
        for (int kk = 0; kk < BKK; kk += 8) {
            u32 a[4][4], bb[4][2];
            #pragma unroll
            for (int mt = 0; mt < 4; mt++) {
                const float* ap = &Asm[(wo + mt * 16 + lq) * APAD + kk + ls];
                a[mt][0] = __float_as_uint(ap[0]);
                a[mt][1] = __float_as_uint(ap[8 * APAD]);
                a[mt][2] = __float_as_uint(ap[4]);
                a[mt][3] = __float_as_uint(ap[8 * APAD + 4]);
            }
            #pragma unroll
            for (int nt = 0; nt < 4; nt++) {
                const float* bp = &Bsm[(kk + ls) * BPAD + wm + nt * 8 + lq];
                bb[nt][0] = __float_as_uint(bp[0]);
                bb[nt][1] = __float_as_uint(bp[4 * BPAD]);
            }
            #pragma unroll
            for (int mt = 0; mt < 4; mt++)
                #pragma unroll
                for (int nt = 0; nt < 4; nt++) {
                    asm volatile(
                        "mma.sync.aligned.m16n8k8.row.col.f32.tf32.tf32.f32 "
                        "{%0,%1,%2,%3}, {%4,%5,%6,%7}, {%8,%9}, {%0,%1,%2,%3};"
                        : "+f"(c[mt][nt][0]), "+f"(c[mt][nt][1]),
                          "+f"(c[mt][nt][2]), "+f"(c[mt][nt][3])
                        : "r"(a[mt][0]), "r"(a[mt][1]), "r"(a[mt][2]), "r"(a[mt][3]),
                          "r"(bb[nt][0]), "r"(bb[nt][1]));
                }
        }
    }

    // epilogue: float2 stores (c0,c1) at (row, col..col+1), (c2,c3) at row+8
    #pragma unroll
    for (int mt = 0; mt < 4; mt++) {
        int row = o0 + wo + mt * 16 + lq;
        #pragma unroll
        for (int nt = 0; nt < 4; nt++) {
            int col = m0 + wm + nt * 8 + ls * 2;
            *(float2*)&outp[(size_t)(b * CD + row) * ldc + col] =
                make_float2(c[mt][nt][0], c[mt][nt][1]);
            *(float2*)&outp[(size_t)(b * CD + row + 8) * ldc + col] =
                make_float2(c[mt][nt][2], c[mt][nt][3]);
        }
    }
}

// ---------------- interp add + BN partial stats (fused) ------------------------
__global__ __launch_bounds__(256) void interp_stats_kernel()
{
    const int o = blockIdx.x, b = blockIdx.y;
    const float* z = g_z + (size_t)(b * CD + o) * SPTS;
    float* yrow = g_y + (size_t)(b * CD + o) * MPTS;
    const int* ki = g_ki + (size_t)b * MPTS * 3;
    const float* kw = g_kw + (size_t)b * MPTS * 3;

    float s = 0.0f, s2 = 0.0f;
    for (int m = threadIdx.x; m < MPTS; m += 256) {
        int i0 = ki[m * 3 + 0], i1 = ki[m * 3 + 1], i2 = ki[m * 3 + 2];
        float w0 = kw[m * 3 + 0], w1 = kw[m * 3 + 1], w2 = kw[m * 3 + 2];
        float v = yrow[m] + w0 * z[i0] + w1 * z[i1] + w2 * z[i2];
        yrow[m] = v;
        s += v; s2 += v * v;
    }
    __shared__ float sh[256], sh2[256];
    sh[threadIdx.x] = s; sh2[threadIdx.x] = s2;
    __syncthreads();
    for (int off = 128; off > 0; off >>= 1) {
        if (threadIdx.x < off) {
            sh[threadIdx.x]  += sh[threadIdx.x + off];
            sh2[threadIdx.x] += sh2[threadIdx.x + off];
        }
        __syncthreads();
    }
    if (threadIdx.x == 0) {
        g_rsum[b * CD + o]  = sh[0];
        g_rsum2[b * CD + o] = sh2[0];
    }
}

// ---------------- BN finalize ---------------------------------------------------
__global__ __launch_bounds__(256) void bn_finalize_kernel(
    const float* __restrict__ gamma, const float* __restrict__ beta)
{
    const int o = threadIdx.x;
    float s = 0.0f, s2 = 0.0f;
    #pragma unroll
    for (int b = 0; b < BATCH; b++) { s += g_rsum[b * CD + o]; s2 += g_rsum2[b * CD + o]; }
    const float invn = 1.0f / (float)(BATCH * MPTS);
    float mean = s * invn;
    float var  = s2 * invn - mean * mean;
    float sc = gamma[o] * rsqrtf(var + 1e-5f);
    g_scale[o] = sc;
    g_bias[o]  = beta[o] - mean * sc;
}

// ---------------- normalize + LeakyReLU ----------------------------------------
__global__ __launch_bounds__(256) void bn_apply_kernel(float* __restrict__ out)
{
    const size_t total4 = (size_t)BATCH * CD * MPTS / 4;
    size_t i4 = (size_t)blockIdx.x * blockDim.x + threadIdx.x;
    if (i4 >= total4) return;
    float4 v = ((const float4*)g_y)[i4];
    int o = (int)((i4 >> 10) & (CD - 1));
    float sc = g_scale[o], bi = g_bias[o];
    float t;
    t = v.x * sc + bi; v.x = (t >= 0.0f) ? t : 0.2f * t;
    t = v.y * sc + bi; v.y = (t >= 0.0f) ? t : 0.2f * t;
    t = v.z * sc + bi; v.z = (t >= 0.0f) ? t : 0.2f * t;
    t = v.w * sc + bi; v.w = (t >= 0.0f) ? t : 0.2f * t;
    ((float4*)out)[i4] = v;
}

__global__ __launch_bounds__(256) void idx_copy_kernel(
    const int* __restrict__ dense_idx, float* __restrict__ out)
{
    int j = blockIdx.x * blockDim.x + threadIdx.x;
    if (j < BATCH * MPTS)
        out[(size_t)BATCH * CD * MPTS + j] = (float)dense_idx[j];
}

// ---------------- host launcher -------------------------------------------------
extern "C" void kernel_launch(void* const* d_in, const int* in_sizes, int n_in,
                              void* d_out, int out_size)
{
    const float* dense_data  = (const float*)d_in[0];
    const int*   dense_idx   = (const int*)  d_in[1];
    const float* sparse_data = (const float*)d_in[2];
    const int*   sparse_idx  = (const int*)  d_in[3];
    const float* pcd         = (const float*)d_in[4];
    const float* conv_w      = (const float*)d_in[5];
    const float* bn_gamma    = (const float*)d_in[6];
    const float* bn_beta     = (const float*)d_in[7];
    float* out = (float*)d_out;

    float* d_z; cudaGetSymbolAddress((void**)&d_z, g_z);
    float* d_y; cudaGetSymbolAddress((void**)&d_y, g_y);

    // 1. KNN (exact fp32)
    knn_kernel<<<dim3(MPTS / 256, BATCH), 256>>>(pcd, dense_idx, sparse_idx);

    // 2. z = W[:,256:768] @ sparse_data    (tf32 mma.sync)
    gemm_mma<CS, CD, SPTS><<<dim3(SPTS / 128, CD / 128, BATCH), 256>>>(
        conv_w, sparse_data, d_z, SPTS);

    // 3. y1 = W[:,0:256] @ dense_data      (tf32 mma.sync)
    gemm_mma<CD, 0, MPTS><<<dim3(MPTS / 128, CD / 128, BATCH), 256>>>(
        conv_w, dense_data, d_y, MPTS);

    // 4. y += knn-interp(z); fused BN partial sums
    interp_stats_kernel<<<dim3(CD, BATCH), 256>>>();

    // 5. BN finalize
    bn_finalize_kernel<<<1, 256>>>(bn_gamma, bn_beta);

    // 6. normalize + leaky relu -> out
    size_t total4 = (size_t)BATCH * CD * MPTS / 4;
    bn_apply_kernel<<<(unsigned)((total4 + 255) / 256), 256>>>(out);

    // 7. tuple tail: dense_idx
    if (out_size >= BATCH * CD * MPTS + BATCH * MPTS)
        idx_copy_kernel<<<(BATCH * MPTS + 255) / 256, 256>>>(dense_idx, out);
}

// round 7
// speedup vs baseline: 2.0478x; 1.1513x over previous
#include <cuda_runtime.h>

#define BATCH 8
#define CD 256
#define CS 512
#define MPTS 4096
#define SPTS 1024
#define NPTS 4096
#define WLD 768

typedef unsigned int u32;

// ---------------- scratch (device globals) -----------------------------------
__device__ float g_z[BATCH * CD * SPTS];          // W2 @ sparse : [b][o][s]
__device__ float g_y[(size_t)BATCH * CD * MPTS];  // pre-BN y    : [b][o][m]
__device__ int   g_ki0[BATCH * MPTS];
__device__ int   g_ki1[BATCH * MPTS];
__device__ int   g_ki2[BATCH * MPTS];
__device__ float g_kw0[BATCH * MPTS];
__device__ float g_kw1[BATCH * MPTS];
__device__ float g_kw2[BATCH * MPTS];
__device__ float g_rsum[BATCH * CD];
__device__ float g_rsum2[BATCH * CD];
__device__ float g_scale[CD];
__device__ float g_bias[CD];

__device__ __forceinline__ float tf32rn(float x) {
    float y;
    asm("cvt.rna.tf32.f32 %0, %1;" : "=f"(y) : "f"(x));
    return y;
}

// ---------------- kernel 1: KNN (exact fp32, bit-matches reference) -----------
__global__ __launch_bounds__(256) void knn_kernel(
    const float* __restrict__ pcd,
    const int* __restrict__ dense_idx,
    const int* __restrict__ sparse_idx)
{
    __shared__ float sx[SPTS], sy[SPTS], sz[SPTS], ss[SPTS];
    const int b = blockIdx.y;
    const float* pb = pcd + (size_t)b * 3 * NPTS;

    for (int s = threadIdx.x; s < SPTS; s += blockDim.x) {
        int si = sparse_idx[b * SPTS + s];
        float x = pb[si], y = pb[NPTS + si], z = pb[2 * NPTS + si];
        ss[s] = __fadd_rn(__fadd_rn(__fmul_rn(x, x), __fmul_rn(y, y)), __fmul_rn(z, z));
        sx[s] = x; sy[s] = y; sz[s] = z;
    }
    __syncthreads();

    const int m = blockIdx.x * blockDim.x + threadIdx.x;
    const int di = dense_idx[b * MPTS + m];
    const float dx = pb[di], dy = pb[NPTS + di], dz = pb[2 * NPTS + di];
    const float dd = __fadd_rn(__fadd_rn(__fmul_rn(dx, dx), __fmul_rn(dy, dy)),
                               __fmul_rn(dz, dz));

    float d0 = 3.4e38f, d1 = 3.4e38f, d2v = 3.4e38f;
    int i0 = 0, i1 = 0, i2 = 0;
    #pragma unroll 4
    for (int s = 0; s < SPTS; s++) {
        float p0 = __fmul_rn(dx, sx[s]);
        float p1 = __fmul_rn(dy, sy[s]);
        float p2 = __fmul_rn(dz, sz[s]);
        float dot = __fadd_rn(__fadd_rn(p0, p1), p2);
        float d2 = __fadd_rn(__fadd_rn(dd, ss[s]), -__fmul_rn(2.0f, dot));
        if (d2 < d0)       { d2v = d1; i2 = i1; d1 = d0; i1 = i0; d0 = d2; i0 = s; }
        else if (d2 < d1)  { d2v = d1; i2 = i1; d1 = d2; i1 = s; }
        else if (d2 < d2v) { d2v = d2; i2 = s; }
    }
    float w0 = __fdiv_rn(1.0f, __fadd_rn(d0,  1e-8f));
    float w1 = __fdiv_rn(1.0f, __fadd_rn(d1,  1e-8f));
    float w2 = __fdiv_rn(1.0f, __fadd_rn(d2v, 1e-8f));
    float sum = __fadd_rn(__fadd_rn(w0, w1), w2);
    int gi = b * MPTS + m;
    g_ki0[gi] = i0; g_ki1[gi] = i1; g_ki2[gi] = i2;
    g_kw0[gi] = __fdiv_rn(w0, sum);
    g_kw1[gi] = __fdiv_rn(w1, sum);
    g_kw2[gi] = __fdiv_rn(w2, sum);
}

// ---------------- tf32 mma.sync GEMM (X-prefetch pipelined) --------------------
// out[b][o0+r][m0+c] = sum_k conv_w[o0+r][WOFF+k] * Xg[b][k][m0+c]
#define BKK 32
#define APAD 36
#define BPAD 136

template<int KDIM, int WOFF, int LDXV>
__global__ __launch_bounds__(256, 2) void gemm_mma(
    const float* __restrict__ conv_w,
    const float* __restrict__ Xg,
    float* __restrict__ outp, int ldc)
{
    __shared__ float Asm[128 * APAD];
    __shared__ float Bsm[BKK * BPAD];

    const int tid  = threadIdx.x;
    const int wid  = tid >> 5;
    const int lane = tid & 31;
    const int lq   = lane >> 2;
    const int ls   = lane & 3;
    const int wo   = (wid >> 2) * 64;
    const int wm   = (wid & 3) * 32;

    const int b  = blockIdx.z;
    const int o0 = blockIdx.y * 128;
    const int m0 = blockIdx.x * 128;
    const float* X = Xg + (size_t)b * KDIM * LDXV;

    // load-index precompute
    const int ao  = tid >> 3, ak4 = tid & 7;          // A: +q*32 rows
    const int bk  = tid >> 5, bm4 = tid & 31;         // B: +q*8  rows

    float c[4][4][4];
    #pragma unroll
    for (int mt = 0; mt < 4; mt++)
        #pragma unroll
        for (int nt = 0; nt < 4; nt++)
            #pragma unroll
            for (int r = 0; r < 4; r++) c[mt][nt][r] = 0.0f;

    // prefetch first X chunk into registers
    float4 xreg[4];
    #pragma unroll
    for (int q = 0; q < 4; q++)
        xreg[q] = *(const float4*)&X[(size_t)(bk + q * 8) * LDXV + m0 + bm4 * 4];

    for (int kt = 0; kt < KDIM; kt += BKK) {
        if (kt) __syncthreads();
        // A chunk (L2-hot weights): load + cvt + store
        #pragma unroll
        for (int q = 0; q < 4; q++) {
            float4 v = *(const float4*)&conv_w[(size_t)(o0 + ao + q * 32) * WLD + WOFF + kt + ak4 * 4];
            float* dst = &Asm[(ao + q * 32) * APAD + ak4 * 4];
            dst[0] = tf32rn(v.x); dst[1] = tf32rn(v.y);
            dst[2] = tf32rn(v.z); dst[3] = tf32rn(v.w);
        }
        // B chunk from prefetch registers
        #pragma unroll
        for (int q = 0; q < 4; q++) {
            float* dst = &Bsm[(bk + q * 8) * BPAD + bm4 * 4];
            dst[0] = tf32rn(xreg[q].x); dst[1] = tf32rn(xreg[q].y);
            dst[2] = tf32rn(xreg[q].z); dst[3] = tf32rn(xreg[q].w);
        }
        __syncthreads();

        // prefetch next X chunk (overlaps with compute below)
        if (kt + BKK < KDIM) {
            #pragma unroll
            for (int q = 0; q < 4; q++)
                xreg[q] = *(const float4*)&X[(size_t)(kt + BKK + bk + q * 8) * LDXV + m0 + bm4 * 4];
        }

        #pragma unroll
        for (int kk = 0; kk < BKK; kk += 8) {
            u32 a[4][4], bb[4][2];
            #pragma unroll
            for (int mt = 0; mt < 4; mt++) {
                const float* ap = &Asm[(wo + mt * 16 + lq) * APAD + kk + ls];
                a[mt][0] = __float_as_uint(ap[0]);
                a[mt][1] = __float_as_uint(ap[8 * APAD]);
                a[mt][2] = __float_as_uint(ap[4]);
                a[mt][3] = __float_as_uint(ap[8 * APAD + 4]);
            }
            #pragma unroll
            for (int nt = 0; nt < 4; nt++) {
                const float* bp = &Bsm[(kk + ls) * BPAD + wm + nt * 8 + lq];
                bb[nt][0] = __float_as_uint(bp[0]);
                bb[nt][1] = __float_as_uint(bp[4 * BPAD]);
            }
            #pragma unroll
            for (int mt = 0; mt < 4; mt++)
                #pragma unroll
                for (int nt = 0; nt < 4; nt++) {
                    asm volatile(
                        "mma.sync.aligned.m16n8k8.row.col.f32.tf32.tf32.f32 "
                        "{%0,%1,%2,%3}, {%4,%5,%6,%7}, {%8,%9}, {%0,%1,%2,%3};"
                        : "+f"(c[mt][nt][0]), "+f"(c[mt][nt][1]),
                          "+f"(c[mt][nt][2]), "+f"(c[mt][nt][3])
                        : "r"(a[mt][0]), "r"(a[mt][1]), "r"(a[mt][2]), "r"(a[mt][3]),
                          "r"(bb[nt][0]), "r"(bb[nt][1]));
                }
        }
    }

    #pragma unroll
    for (int mt = 0; mt < 4; mt++) {
        int row = o0 + wo + mt * 16 + lq;
        #pragma unroll
        for (int nt = 0; nt < 4; nt++) {
            int col = m0 + wm + nt * 8 + ls * 2;
            *(float2*)&outp[(size_t)(b * CD + row) * ldc + col] =
                make_float2(c[mt][nt][0], c[mt][nt][1]);
            *(float2*)&outp[(size_t)(b * CD + row + 8) * ldc + col] =
                make_float2(c[mt][nt][2], c[mt][nt][3]);
        }
    }
}

// ---------------- interp add + BN partial stats (vectorized, SoA) --------------
__global__ __launch_bounds__(256) void interp_stats_kernel()
{
    const int o = blockIdx.x, b = blockIdx.y;
    const float* z = g_z + (size_t)(b * CD + o) * SPTS;
    float4* yrow = (float4*)(g_y + (size_t)(b * CD + o) * MPTS);
    const int4*   ki0 = (const int4*)  (g_ki0 + (size_t)b * MPTS);
    const int4*   ki1 = (const int4*)  (g_ki1 + (size_t)b * MPTS);
    const int4*   ki2 = (const int4*)  (g_ki2 + (size_t)b * MPTS);
    const float4* kw0 = (const float4*)(g_kw0 + (size_t)b * MPTS);
    const float4* kw1 = (const float4*)(g_kw1 + (size_t)b * MPTS);
    const float4* kw2 = (const float4*)(g_kw2 + (size_t)b * MPTS);

    float s = 0.0f, s2 = 0.0f;
    #pragma unroll 2
    for (int m4 = threadIdx.x; m4 < MPTS / 4; m4 += 256) {
        int4   a0 = ki0[m4], a1 = ki1[m4], a2 = ki2[m4];
        float4 w0 = kw0[m4], w1 = kw1[m4], w2 = kw2[m4];
        float4 v = yrow[m4];
        v.x += w0.x * z[a0.x] + w1.x * z[a1.x] + w2.x * z[a2.x];
        v.y += w0.y * z[a0.y] + w1.y * z[a1.y] + w2.y * z[a2.y];
        v.z += w0.z * z[a0.z] + w1.z * z[a1.z] + w2.z * z[a2.z];
        v.w += w0.w * z[a0.w] + w1.w * z[a1.w] + w2.w * z[a2.w];
        yrow[m4] = v;
        s  += v.x + v.y + v.z + v.w;
        s2 += v.x * v.x + v.y * v.y + v.z * v.z + v.w * v.w;
    }
    __shared__ float sh[256], sh2[256];
    sh[threadIdx.x] = s; sh2[threadIdx.x] = s2;
    __syncthreads();
    for (int off = 128; off > 0; off >>= 1) {
        if (threadIdx.x < off) {
            sh[threadIdx.x]  += sh[threadIdx.x + off];
            sh2[threadIdx.x] += sh2[threadIdx.x + off];
        }
        __syncthreads();
    }
    if (threadIdx.x == 0) {
        g_rsum[b * CD + o]  = sh[0];
        g_rsum2[b * CD + o] = sh2[0];
    }
}

// ---------------- BN finalize ---------------------------------------------------
__global__ __launch_bounds__(256) void bn_finalize_kernel(
    const float* __restrict__ gamma, const float* __restrict__ beta)
{
    const int o = threadIdx.x;
    float s = 0.0f, s2 = 0.0f;
    #pragma unroll
    for (int b = 0; b < BATCH; b++) { s += g_rsum[b * CD + o]; s2 += g_rsum2[b * CD + o]; }
    const float invn = 1.0f / (float)(BATCH * MPTS);
    float mean = s * invn;
    float var  = s2 * invn - mean * mean;
    float sc = gamma[o] * rsqrtf(var + 1e-5f);
    g_scale[o] = sc;
    g_bias[o]  = beta[o] - mean * sc;
}

// ---------------- normalize + LeakyReLU ----------------------------------------
__global__ __launch_bounds__(256) void bn_apply_kernel(float* __restrict__ out)
{
    const size_t total4 = (size_t)BATCH * CD * MPTS / 4;
    size_t i4 = (size_t)blockIdx.x * blockDim.x + threadIdx.x;
    if (i4 >= total4) return;
    float4 v = ((const float4*)g_y)[i4];
    int o = (int)((i4 >> 10) & (CD - 1));
    float sc = g_scale[o], bi = g_bias[o];
    float t;
    t = v.x * sc + bi; v.x = (t >= 0.0f) ? t : 0.2f * t;
    t = v.y * sc + bi; v.y = (t >= 0.0f) ? t : 0.2f * t;
    t = v.z * sc + bi; v.z = (t >= 0.0f) ? t : 0.2f * t;
    t = v.w * sc + bi; v.w = (t >= 0.0f) ? t : 0.2f * t;
    ((float4*)out)[i4] = v;
}

__global__ __launch_bounds__(256) void idx_copy_kernel(
    const int* __restrict__ dense_idx, float* __restrict__ out)
{
    int j = blockIdx.x * blockDim.x + threadIdx.x;
    if (j < BATCH * MPTS)
        out[(size_t)BATCH * CD * MPTS + j] = (float)dense_idx[j];
}

// ---------------- host launcher -------------------------------------------------
extern "C" void kernel_launch(void* const* d_in, const int* in_sizes, int n_in,
                              void* d_out, int out_size)
{
    const float* dense_data  = (const float*)d_in[0];
    const int*   dense_idx   = (const int*)  d_in[1];
    const float* sparse_data = (const float*)d_in[2];
    const int*   sparse_idx  = (const int*)  d_in[3];
    const float* pcd         = (const float*)d_in[4];
    const float* conv_w      = (const float*)d_in[5];
    const float* bn_gamma    = (const float*)d_in[6];
    const float* bn_beta     = (const float*)d_in[7];
    float* out = (float*)d_out;

    float* d_z; cudaGetSymbolAddress((void**)&d_z, g_z);
    float* d_y; cudaGetSymbolAddress((void**)&d_y, g_y);

    // 1. KNN (exact fp32)
    knn_kernel<<<dim3(MPTS / 256, BATCH), 256>>>(pcd, dense_idx, sparse_idx);

    // 2. z = W[:,256:768] @ sparse_data    (tf32 mma.sync)
    gemm_mma<CS, CD, SPTS><<<dim3(SPTS / 128, CD / 128, BATCH), 256>>>(
        conv_w, sparse_data, d_z, SPTS);

    // 3. y1 = W[:,0:256] @ dense_data      (tf32 mma.sync)
    gemm_mma<CD, 0, MPTS><<<dim3(MPTS / 128, CD / 128, BATCH), 256>>>(
        conv_w, dense_data, d_y, MPTS);

    // 4. y += knn-interp(z); fused BN partial sums
    interp_stats_kernel<<<dim3(CD, BATCH), 256>>>();

    // 5. BN finalize
    bn_finalize_kernel<<<1, 256>>>(bn_gamma, bn_beta);

    // 6. normalize + leaky relu -> out
    size_t total4 = (size_t)BATCH * CD * MPTS / 4;
    bn_apply_kernel<<<(unsigned)((total4 + 255) / 256), 256>>>(out);

    // 7. tuple tail: dense_idx
    if (out_size >= BATCH * CD * MPTS + BATCH * MPTS)
        idx_copy_kernel<<<(BATCH * MPTS + 255) / 256, 256>>>(dense_idx, out);
}

// round 8
// speedup vs baseline: 2.2671x; 1.1071x over previous
#include <cuda_runtime.h>

#define BATCH 8
#define CD 256
#define CS 512
#define MPTS 4096
#define SPTS 1024
#define NPTS 4096
#define WLD 768

typedef unsigned int u32;

// ---------------- scratch (device globals) -----------------------------------
__device__ float g_z[BATCH * CD * SPTS];          // W2 @ sparse : [b][o][s]
__device__ float g_y[(size_t)BATCH * CD * MPTS];  // pre-BN y    : [b][o][m]
__device__ int   g_ki0[BATCH * MPTS];
__device__ int   g_ki1[BATCH * MPTS];
__device__ int   g_ki2[BATCH * MPTS];
__device__ float g_kw0[BATCH * MPTS];
__device__ float g_kw1[BATCH * MPTS];
__device__ float g_kw2[BATCH * MPTS];
__device__ float g_rsum[BATCH * CD];
__device__ float g_rsum2[BATCH * CD];
__device__ float g_scale[CD];
__device__ float g_bias[CD];

__device__ __forceinline__ float tf32rn(float x) {
    float y;
    asm("cvt.rna.tf32.f32 %0, %1;" : "=f"(y) : "f"(x));
    return y;
}

// ---------------- kernel 1: KNN (exact fp32, bit-matches reference) -----------
__global__ __launch_bounds__(256) void knn_kernel(
    const float* __restrict__ pcd,
    const int* __restrict__ dense_idx,
    const int* __restrict__ sparse_idx)
{
    __shared__ float sx[SPTS], sy[SPTS], sz[SPTS], ss[SPTS];
    const int b = blockIdx.y;
    const float* pb = pcd + (size_t)b * 3 * NPTS;

    for (int s = threadIdx.x; s < SPTS; s += blockDim.x) {
        int si = sparse_idx[b * SPTS + s];
        float x = pb[si], y = pb[NPTS + si], z = pb[2 * NPTS + si];
        ss[s] = __fadd_rn(__fadd_rn(__fmul_rn(x, x), __fmul_rn(y, y)), __fmul_rn(z, z));
        sx[s] = x; sy[s] = y; sz[s] = z;
    }
    __syncthreads();

    const int m = blockIdx.x * blockDim.x + threadIdx.x;
    const int di = dense_idx[b * MPTS + m];
    const float dx = pb[di], dy = pb[NPTS + di], dz = pb[2 * NPTS + di];
    const float dd = __fadd_rn(__fadd_rn(__fmul_rn(dx, dx), __fmul_rn(dy, dy)),
                               __fmul_rn(dz, dz));

    float d0 = 3.4e38f, d1 = 3.4e38f, d2v = 3.4e38f;
    int i0 = 0, i1 = 0, i2 = 0;
    #pragma unroll 4
    for (int s = 0; s < SPTS; s++) {
        float p0 = __fmul_rn(dx, sx[s]);
        float p1 = __fmul_rn(dy, sy[s]);
        float p2 = __fmul_rn(dz, sz[s]);
        float dot = __fadd_rn(__fadd_rn(p0, p1), p2);
        float d2 = __fadd_rn(__fadd_rn(dd, ss[s]), -__fmul_rn(2.0f, dot));
        if (d2 < d0)       { d2v = d1; i2 = i1; d1 = d0; i1 = i0; d0 = d2; i0 = s; }
        else if (d2 < d1)  { d2v = d1; i2 = i1; d1 = d2; i1 = s; }
        else if (d2 < d2v) { d2v = d2; i2 = s; }
    }
    float w0 = __fdiv_rn(1.0f, __fadd_rn(d0,  1e-8f));
    float w1 = __fdiv_rn(1.0f, __fadd_rn(d1,  1e-8f));
    float w2 = __fdiv_rn(1.0f, __fadd_rn(d2v, 1e-8f));
    float sum = __fadd_rn(__fadd_rn(w0, w1), w2);
    int gi = b * MPTS + m;
    g_ki0[gi] = i0; g_ki1[gi] = i1; g_ki2[gi] = i2;
    g_kw0[gi] = __fdiv_rn(w0, sum);
    g_kw1[gi] = __fdiv_rn(w1, sum);
    g_kw2[gi] = __fdiv_rn(w2, sum);
}

// ---------------- merged tf32 mma.sync GEMM (z + y in one launch) --------------
// z blocks (flat 0..127):  out=g_z, K=512, WOFF=256, X=sparse (ld 1024), 8 m-tiles
// y blocks (flat 128..639):out=g_y, K=256, WOFF=0,   X=dense  (ld 4096), 32 m-tiles
#define BKK 32
#define APAD 36
#define BPAD 136
#define NZBLK 128   // 8 mtiles * 2 otiles * 8 batches

__global__ __launch_bounds__(256, 2) void gemm_mma_all(
    const float* __restrict__ conv_w,
    const float* __restrict__ dense_data,
    const float* __restrict__ sparse_data,
    float* __restrict__ gy, float* __restrict__ gz)
{
    __shared__ float Asm[128 * APAD];
    __shared__ float Bsm[BKK * BPAD];

    const int flat = blockIdx.x;
    const bool isZ = flat < NZBLK;

    int KDIM, WOFF, LDXV, ldc, mtiles, idx;
    const float* Xbase; float* outp;
    if (isZ) { KDIM = CS; WOFF = CD; LDXV = SPTS; ldc = SPTS; mtiles = 8;
               Xbase = sparse_data; outp = gz; idx = flat; }
    else     { KDIM = CD; WOFF = 0;  LDXV = MPTS; ldc = MPTS; mtiles = 32;
               Xbase = dense_data; outp = gy; idx = flat - NZBLK; }

    const int mtile = idx % mtiles;
    const int otile = (idx / mtiles) & 1;
    const int b     = idx / (mtiles * 2);
    const int m0 = mtile * 128;
    const int o0 = otile * 128;
    const float* X = Xbase + (size_t)b * KDIM * LDXV;

    const int tid  = threadIdx.x;
    const int wid  = tid >> 5;
    const int lane = tid & 31;
    const int lq   = lane >> 2;
    const int ls   = lane & 3;
    const int wo   = (wid >> 2) * 64;
    const int wm   = (wid & 3) * 32;

    const int ao  = tid >> 3, ak4 = tid & 7;
    const int bk  = tid >> 5, bm4 = tid & 31;

    float c[4][4][4];
    #pragma unroll
    for (int mt = 0; mt < 4; mt++)
        #pragma unroll
        for (int nt = 0; nt < 4; nt++)
            #pragma unroll
            for (int r = 0; r < 4; r++) c[mt][nt][r] = 0.0f;

    float4 xreg[4];
    #pragma unroll
    for (int q = 0; q < 4; q++)
        xreg[q] = *(const float4*)&X[(size_t)(bk + q * 8) * LDXV + m0 + bm4 * 4];

    for (int kt = 0; kt < KDIM; kt += BKK) {
        if (kt) __syncthreads();
        #pragma unroll
        for (int q = 0; q < 4; q++) {
            float4 v = *(const float4*)&conv_w[(size_t)(o0 + ao + q * 32) * WLD + WOFF + kt + ak4 * 4];
            float* dst = &Asm[(ao + q * 32) * APAD + ak4 * 4];
            dst[0] = tf32rn(v.x); dst[1] = tf32rn(v.y);
            dst[2] = tf32rn(v.z); dst[3] = tf32rn(v.w);
        }
        #pragma unroll
        for (int q = 0; q < 4; q++) {
            float* dst = &Bsm[(bk + q * 8) * BPAD + bm4 * 4];
            dst[0] = tf32rn(xreg[q].x); dst[1] = tf32rn(xreg[q].y);
            dst[2] = tf32rn(xreg[q].z); dst[3] = tf32rn(xreg[q].w);
        }
        __syncthreads();

        if (kt + BKK < KDIM) {
            #pragma unroll
            for (int q = 0; q < 4; q++)
                xreg[q] = *(const float4*)&X[(size_t)(kt + BKK + bk + q * 8) * LDXV + m0 + bm4 * 4];
        }

        #pragma unroll
        for (int kk = 0; kk < BKK; kk += 8) {
            u32 a[4][4], bb[4][2];
            #pragma unroll
            for (int mt = 0; mt < 4; mt++) {
                const float* ap = &Asm[(wo + mt * 16 + lq) * APAD + kk + ls];
                a[mt][0] = __float_as_uint(ap[0]);
                a[mt][1] = __float_as_uint(ap[8 * APAD]);
                a[mt][2] = __float_as_uint(ap[4]);
                a[mt][3] = __float_as_uint(ap[8 * APAD + 4]);
            }
            #pragma unroll
            for (int nt = 0; nt < 4; nt++) {
                const float* bp = &Bsm[(kk + ls) * BPAD + wm + nt * 8 + lq];
                bb[nt][0] = __float_as_uint(bp[0]);
                bb[nt][1] = __float_as_uint(bp[4 * BPAD]);
            }
            #pragma unroll
            for (int mt = 0; mt < 4; mt++)
                #pragma unroll
                for (int nt = 0; nt < 4; nt++) {
                    asm volatile(
                        "mma.sync.aligned.m16n8k8.row.col.f32.tf32.tf32.f32 "
                        "{%0,%1,%2,%3}, {%4,%5,%6,%7}, {%8,%9}, {%0,%1,%2,%3};"
                        : "+f"(c[mt][nt][0]), "+f"(c[mt][nt][1]),
                          "+f"(c[mt][nt][2]), "+f"(c[mt][nt][3])
                        : "r"(a[mt][0]), "r"(a[mt][1]), "r"(a[mt][2]), "r"(a[mt][3]),
                          "r"(bb[nt][0]), "r"(bb[nt][1]));
                }
        }
    }

    #pragma unroll
    for (int mt = 0; mt < 4; mt++) {
        int row = o0 + wo + mt * 16 + lq;
        #pragma unroll
        for (int nt = 0; nt < 4; nt++) {
            int col = m0 + wm + nt * 8 + ls * 2;
            *(float2*)&outp[(size_t)(b * CD + row) * ldc + col] =
                make_float2(c[mt][nt][0], c[mt][nt][1]);
            *(float2*)&outp[(size_t)(b * CD + row + 8) * ldc + col] =
                make_float2(c[mt][nt][2], c[mt][nt][3]);
        }
    }
}

// ---------------- interp add + BN partial stats (smem z gathers) ---------------
__global__ __launch_bounds__(256) void interp_stats_kernel()
{
    __shared__ float zs[SPTS];
    const int o = blockIdx.x, b = blockIdx.y;
    const float4* zin = (const float4*)(g_z + (size_t)(b * CD + o) * SPTS);
    #pragma unroll
    for (int q = 0; q < SPTS / 4 / 256; q++)
        ((float4*)zs)[threadIdx.x + q * 256] = zin[threadIdx.x + q * 256];
    __syncthreads();

    float4* yrow = (float4*)(g_y + (size_t)(b * CD + o) * MPTS);
    const int4*   ki0 = (const int4*)  (g_ki0 + (size_t)b * MPTS);
    const int4*   ki1 = (const int4*)  (g_ki1 + (size_t)b * MPTS);
    const int4*   ki2 = (const int4*)  (g_ki2 + (size_t)b * MPTS);
    const float4* kw0 = (const float4*)(g_kw0 + (size_t)b * MPTS);
    const float4* kw1 = (const float4*)(g_kw1 + (size_t)b * MPTS);
    const float4* kw2 = (const float4*)(g_kw2 + (size_t)b * MPTS);

    float s = 0.0f, s2 = 0.0f;
    #pragma unroll
    for (int q = 0; q < MPTS / 4 / 256; q++) {
        int m4 = threadIdx.x + q * 256;
        int4   a0 = ki0[m4], a1 = ki1[m4], a2 = ki2[m4];
        float4 w0 = kw0[m4], w1 = kw1[m4], w2 = kw2[m4];
        float4 v = yrow[m4];
        v.x += w0.x * zs[a0.x] + w1.x * zs[a1.x] + w2.x * zs[a2.x];
        v.y += w0.y * zs[a0.y] + w1.y * zs[a1.y] + w2.y * zs[a2.y];
        v.z += w0.z * zs[a0.z] + w1.z * zs[a1.z] + w2.z * zs[a2.z];
        v.w += w0.w * zs[a0.w] + w1.w * zs[a1.w] + w2.w * zs[a2.w];
        yrow[m4] = v;
        s  += v.x + v.y + v.z + v.w;
        s2 += v.x * v.x + v.y * v.y + v.z * v.z + v.w * v.w;
    }
    __shared__ float sh[256], sh2[256];
    sh[threadIdx.x] = s; sh2[threadIdx.x] = s2;
    __syncthreads();
    for (int off = 128; off > 0; off >>= 1) {
        if (threadIdx.x < off) {
            sh[threadIdx.x]  += sh[threadIdx.x + off];
            sh2[threadIdx.x] += sh2[threadIdx.x + off];
        }
        __syncthreads();
    }
    if (threadIdx.x == 0) {
        g_rsum[b * CD + o]  = sh[0];
        g_rsum2[b * CD + o] = sh2[0];
    }
}

// ---------------- BN finalize ---------------------------------------------------
__global__ __launch_bounds__(256) void bn_finalize_kernel(
    const float* __restrict__ gamma, const float* __restrict__ beta)
{
    const int o = threadIdx.x;
    float s = 0.0f, s2 = 0.0f;
    #pragma unroll
    for (int b = 0; b < BATCH; b++) { s += g_rsum[b * CD + o]; s2 += g_rsum2[b * CD + o]; }
    const float invn = 1.0f / (float)(BATCH * MPTS);
    float mean = s * invn;
    float var  = s2 * invn - mean * mean;
    float sc = gamma[o] * rsqrtf(var + 1e-5f);
    g_scale[o] = sc;
    g_bias[o]  = beta[o] - mean * sc;
}

// ---------------- normalize + LeakyReLU + idx tail (merged) --------------------
#define NB_APPLY ((BATCH * CD * MPTS / 4 + 255) / 256)   // 8192 blocks
__global__ __launch_bounds__(256) void bn_apply_kernel(
    const int* __restrict__ dense_idx, float* __restrict__ out, int out_size)
{
    if (blockIdx.x < NB_APPLY) {
        size_t i4 = (size_t)blockIdx.x * 256 + threadIdx.x;
        float4 v = ((const float4*)g_y)[i4];
        int o = (int)((i4 >> 10) & (CD - 1));
        float sc = g_scale[o], bi = g_bias[o];
        float t;
        t = v.x * sc + bi; v.x = (t >= 0.0f) ? t : 0.2f * t;
        t = v.y * sc + bi; v.y = (t >= 0.0f) ? t : 0.2f * t;
        t = v.z * sc + bi; v.z = (t >= 0.0f) ? t : 0.2f * t;
        t = v.w * sc + bi; v.w = (t >= 0.0f) ? t : 0.2f * t;
        ((float4*)out)[i4] = v;
    } else {
        int j = (blockIdx.x - NB_APPLY) * 256 + threadIdx.x;
        if (j < BATCH * MPTS && out_size >= BATCH * CD * MPTS + BATCH * MPTS)
            out[(size_t)BATCH * CD * MPTS + j] = (float)dense_idx[j];
    }
}

// ---------------- host launcher -------------------------------------------------
extern "C" void kernel_launch(void* const* d_in, const int* in_sizes, int n_in,
                              void* d_out, int out_size)
{
    const float* dense_data  = (const float*)d_in[0];
    const int*   dense_idx   = (const int*)  d_in[1];
    const float* sparse_data = (const float*)d_in[2];
    const int*   sparse_idx  = (const int*)  d_in[3];
    const float* pcd         = (const float*)d_in[4];
    const float* conv_w      = (const float*)d_in[5];
    const float* bn_gamma    = (const float*)d_in[6];
    const float* bn_beta     = (const float*)d_in[7];
    float* out = (float*)d_out;

    float* d_z; cudaGetSymbolAddress((void**)&d_z, g_z);
    float* d_y; cudaGetSymbolAddress((void**)&d_y, g_y);

    // 1. KNN (exact fp32)
    knn_kernel<<<dim3(MPTS / 256, BATCH), 256>>>(pcd, dense_idx, sparse_idx);

    // 2+3. merged z & y GEMMs (z tiles first: they run 2x K-depth)
    gemm_mma_all<<<NZBLK + (MPTS / 128) * 2 * BATCH, 256>>>(
        conv_w, dense_data, sparse_data, d_y, d_z);

    // 4. y += knn-interp(z); fused BN partial sums (smem gathers)
    interp_stats_kernel<<<dim3(CD, BATCH), 256>>>();

    // 5. BN finalize
    bn_finalize_kernel<<<1, 256>>>(bn_gamma, bn_beta);

    // 6. normalize + leaky relu -> out, plus dense_idx tail
    int nb_idx = (BATCH * MPTS + 255) / 256;
    bn_apply_kernel<<<NB_APPLY + nb_idx, 256>>>(dense_idx, out, out_size);
}